// round 9
// baseline (speedup 1.0000x reference)
#include <cuda_runtime.h>
#include <math.h>

#define D 512
#define WARPS_PER_BLOCK 8
#define THREADS (WARPS_PER_BLOCK * 32)

#define SQRT_C 0.1f
#define MIN_NORM 1e-5f
#define EPS 1e-5f

__device__ __forceinline__ float artanh_clamped(float x) {
    x = fminf(fmaxf(x, -1.0f + EPS), 1.0f - EPS);
    return atanhf(x);
}

__global__ void __launch_bounds__(THREADS, 8)
hyp_adapter_kernel(const float* __restrict__ params,
                   const float* __restrict__ weights,
                   float* __restrict__ out,
                   int n_rows)
{
    __shared__ float ws[D];
    for (int i = threadIdx.x; i < D; i += THREADS)
        ws[i] = weights[i];
    __syncthreads();

    const int warp = threadIdx.x >> 5;
    const int lane = threadIdx.x & 31;
    const int row  = blockIdx.x * WARPS_PER_BLOCK + warp;
    if (row >= n_rows) return;

    const float4* __restrict__ p4 = reinterpret_cast<const float4*>(params) + (size_t)row * (D / 4);
    const float4* __restrict__ w4 = reinterpret_cast<const float4*>(ws);
    float4*       __restrict__ o4 = reinterpret_cast<float4*>(out) + (size_t)row * (D / 4);

    // Front-batch all 4 128-bit global loads (coalesced 128B/step, MLP=4).
    float4 pv[4];
#pragma unroll
    for (int j = 0; j < 4; j++)
        pv[j] = p4[j * 32 + lane];

    float4 mv[4];   // w_i * p_i, kept live for the write-back (params read exactly once)
    float s1 = 0.0f;  // sum p^2
    float s2 = 0.0f;  // sum (w*p)^2

#pragma unroll
    for (int j = 0; j < 4; j++) {
        float4 wv = w4[j * 32 + lane];
        s1 = fmaf(pv[j].x, pv[j].x, s1);
        s1 = fmaf(pv[j].y, pv[j].y, s1);
        s1 = fmaf(pv[j].z, pv[j].z, s1);
        s1 = fmaf(pv[j].w, pv[j].w, s1);
        float4 m;
        m.x = pv[j].x * wv.x;
        m.y = pv[j].y * wv.y;
        m.z = pv[j].z * wv.z;
        m.w = pv[j].w * wv.w;
        s2 = fmaf(m.x, m.x, s2);
        s2 = fmaf(m.y, m.y, s2);
        s2 = fmaf(m.z, m.z, s2);
        s2 = fmaf(m.w, m.w, s2);
        mv[j] = m;
    }

    // Warp butterfly reduction; the two chains interleave so SHFL latencies overlap.
#pragma unroll
    for (int off = 16; off > 0; off >>= 1) {
        s1 += __shfl_xor_sync(0xFFFFFFFFu, s1, off);
        s2 += __shfl_xor_sync(0xFFFFFFFFu, s2, off);
    }

    // --- scalar pipeline: out_i = F * w_i * p_i with F from the two row norms ---
    const float r1 = sqrtf(s1);                    // ||params||
    const float u_norm = fmaxf(r1, MIN_NORM);
    const float a = tanhf(SQRT_C * u_norm) / (SQRT_C * u_norm);  // expmap0 scale
    const float x_norm = fmaxf(a * r1, MIN_NORM);                // ||x|| clamped
    const float mx_norm = a * sqrtf(s2);                         // ||mx|| (NOT clamped)

    const float at1 = artanh_clamped(SQRT_C * x_norm);
    const float b = tanhf(mx_norm / x_norm * at1) / (mx_norm * SQRT_C);  // mobius scale
    const float res_norm = b * mx_norm;                                   // ||res||

    const float y_norm = fmaxf(res_norm, MIN_NORM);
    const float maxnorm = (1.0f - 0.001f) / SQRT_C;              // 9.99
    const float g = (y_norm > maxnorm) ? (maxnorm / y_norm) : 1.0f;  // project
    const float yn2 = fmaxf(g * res_norm, MIN_NORM);             // ||y|| clamped
    const float h = artanh_clamped(SQRT_C * yn2) / (yn2 * SQRT_C);   // logmap0 scale

    const float F = h * g * b * a;

#pragma unroll
    for (int j = 0; j < 4; j++) {
        float4 m = mv[j];
        float4 o;
        o.x = F * m.x;
        o.y = F * m.y;
        o.z = F * m.z;
        o.w = F * m.w;
        o4[j * 32 + lane] = o;
    }
}

extern "C" void kernel_launch(void* const* d_in, const int* in_sizes, int n_in,
                              void* d_out, int out_size) {
    const float* params  = (const float*)d_in[0];
    const float* weights = (const float*)d_in[1];
    float* out = (float*)d_out;

    const int n_rows = in_sizes[0] / D;   // 131072
    const int grid = (n_rows + WARPS_PER_BLOCK - 1) / WARPS_PER_BLOCK;
    hyp_adapter_kernel<<<grid, THREADS>>>(params, weights, out, n_rows);
}

// round 10
// speedup vs baseline: 1.0186x; 1.0186x over previous
#include <cuda_runtime.h>
#include <math.h>

#define D 512
#define WARPS_PER_BLOCK 8
#define THREADS (WARPS_PER_BLOCK * 32)

#define SQRT_C 0.1f
#define MIN_NORM 1e-5f
#define EPS 1e-5f

__device__ __forceinline__ float artanh_clamped(float x) {
    x = fminf(fmaxf(x, -1.0f + EPS), 1.0f - EPS);
    return atanhf(x);
}

__global__ void __launch_bounds__(THREADS, 8)
hyp_adapter_kernel(const float* __restrict__ params,
                   const float* __restrict__ weights,
                   float* __restrict__ out,
                   int n_rows)
{
    __shared__ float ws[D];
    for (int i = threadIdx.x; i < D; i += THREADS)
        ws[i] = weights[i];
    __syncthreads();

    const int warp = threadIdx.x >> 5;
    const int lane = threadIdx.x & 31;
    const int row  = blockIdx.x * WARPS_PER_BLOCK + warp;
    if (row >= n_rows) return;

    const float4* __restrict__ p4 = reinterpret_cast<const float4*>(params) + (size_t)row * (D / 4);
    const float4* __restrict__ w4 = reinterpret_cast<const float4*>(ws);
    float4*       __restrict__ o4 = reinterpret_cast<float4*>(out) + (size_t)row * (D / 4);

    // Front-batch all 4 global loads (streaming, evict-first) for MLP=4.
    float4 pv[4];
#pragma unroll
    for (int j = 0; j < 4; j++)
        pv[j] = __ldcs(&p4[j * 32 + lane]);

    float4 mv[4];   // w_i * p_i, kept live for the write-back (params read exactly once)
    float s1 = 0.0f;  // sum p^2
    float s2 = 0.0f;  // sum (w*p)^2

#pragma unroll
    for (int j = 0; j < 4; j++) {
        float4 wv = w4[j * 32 + lane];
        s1 = fmaf(pv[j].x, pv[j].x, s1);
        s1 = fmaf(pv[j].y, pv[j].y, s1);
        s1 = fmaf(pv[j].z, pv[j].z, s1);
        s1 = fmaf(pv[j].w, pv[j].w, s1);
        float4 m;
        m.x = pv[j].x * wv.x;
        m.y = pv[j].y * wv.y;
        m.z = pv[j].z * wv.z;
        m.w = pv[j].w * wv.w;
        s2 = fmaf(m.x, m.x, s2);
        s2 = fmaf(m.y, m.y, s2);
        s2 = fmaf(m.z, m.z, s2);
        s2 = fmaf(m.w, m.w, s2);
        mv[j] = m;
    }

    // Warp butterfly reduction; the two chains interleave so SHFL latencies overlap.
#pragma unroll
    for (int off = 16; off > 0; off >>= 1) {
        s1 += __shfl_xor_sync(0xFFFFFFFFu, s1, off);
        s2 += __shfl_xor_sync(0xFFFFFFFFu, s2, off);
    }

    // --- scalar pipeline: out_i = F * w_i * p_i with F from the two row norms ---
    const float r1 = sqrtf(s1);                    // ||params||
    const float u_norm = fmaxf(r1, MIN_NORM);
    const float a = tanhf(SQRT_C * u_norm) / (SQRT_C * u_norm);  // expmap0 scale
    const float x_norm = fmaxf(a * r1, MIN_NORM);                // ||x|| clamped
    const float mx_norm = a * sqrtf(s2);                         // ||mx|| (NOT clamped)

    const float at1 = artanh_clamped(SQRT_C * x_norm);
    const float b = tanhf(mx_norm / x_norm * at1) / (mx_norm * SQRT_C);  // mobius scale
    const float res_norm = b * mx_norm;                                   // ||res||

    const float y_norm = fmaxf(res_norm, MIN_NORM);
    const float maxnorm = (1.0f - 0.001f) / SQRT_C;              // 9.99
    const float g = (y_norm > maxnorm) ? (maxnorm / y_norm) : 1.0f;  // project
    const float yn2 = fmaxf(g * res_norm, MIN_NORM);             // ||y|| clamped
    const float h = artanh_clamped(SQRT_C * yn2) / (yn2 * SQRT_C);   // logmap0 scale

    const float F = h * g * b * a;

#pragma unroll
    for (int j = 0; j < 4; j++) {
        float4 m = mv[j];
        float4 o;
        o.x = F * m.x;
        o.y = F * m.y;
        o.z = F * m.z;
        o.w = F * m.w;
        __stcs(&o4[j * 32 + lane], o);
    }
}

extern "C" void kernel_launch(void* const* d_in, const int* in_sizes, int n_in,
                              void* d_out, int out_size) {
    const float* params  = (const float*)d_in[0];
    const float* weights = (const float*)d_in[1];
    float* out = (float*)d_out;

    const int n_rows = in_sizes[0] / D;   // 131072
    const int grid = (n_rows + WARPS_PER_BLOCK - 1) / WARPS_PER_BLOCK;
    hyp_adapter_kernel<<<grid, THREADS>>>(params, weights, out, n_rows);
}

// round 13
// speedup vs baseline: 1.0234x; 1.0047x over previous
#include <cuda_runtime.h>
#include <math.h>

#define D 512
#define WARPS_PER_BLOCK 16
#define THREADS (WARPS_PER_BLOCK * 32)

#define SQRT_C 0.1f
#define MIN_NORM 1e-5f
#define EPS 1e-5f

__device__ __forceinline__ float artanh_clamped(float x) {
    x = fminf(fmaxf(x, -1.0f + EPS), 1.0f - EPS);
    return atanhf(x);
}

__global__ void __launch_bounds__(THREADS, 4)
hyp_adapter_kernel(const float* __restrict__ params,
                   const float* __restrict__ weights,
                   float* __restrict__ out,
                   int n_rows)
{
    __shared__ float ws[D];
    for (int i = threadIdx.x; i < D; i += THREADS)
        ws[i] = weights[i];
    __syncthreads();

    const int warp = threadIdx.x >> 5;
    const int lane = threadIdx.x & 31;
    const int row  = blockIdx.x * WARPS_PER_BLOCK + warp;
    if (row >= n_rows) return;

    const float4* __restrict__ p4 = reinterpret_cast<const float4*>(params) + (size_t)row * (D / 4);
    const float4* __restrict__ w4 = reinterpret_cast<const float4*>(ws);
    float4*       __restrict__ o4 = reinterpret_cast<float4*>(out) + (size_t)row * (D / 4);

    // Front-batch all 4 global loads (streaming, evict-first) for MLP=4.
    float4 pv[4];
#pragma unroll
    for (int j = 0; j < 4; j++)
        pv[j] = __ldcs(&p4[j * 32 + lane]);

    float4 mv[4];   // w_i * p_i, kept live for the write-back (params read exactly once)
    float s1 = 0.0f;  // sum p^2
    float s2 = 0.0f;  // sum (w*p)^2

#pragma unroll
    for (int j = 0; j < 4; j++) {
        float4 wv = w4[j * 32 + lane];
        s1 = fmaf(pv[j].x, pv[j].x, s1);
        s1 = fmaf(pv[j].y, pv[j].y, s1);
        s1 = fmaf(pv[j].z, pv[j].z, s1);
        s1 = fmaf(pv[j].w, pv[j].w, s1);
        float4 m;
        m.x = pv[j].x * wv.x;
        m.y = pv[j].y * wv.y;
        m.z = pv[j].z * wv.z;
        m.w = pv[j].w * wv.w;
        s2 = fmaf(m.x, m.x, s2);
        s2 = fmaf(m.y, m.y, s2);
        s2 = fmaf(m.z, m.z, s2);
        s2 = fmaf(m.w, m.w, s2);
        mv[j] = m;
    }

    // Warp butterfly reduction; the two chains interleave so SHFL latencies overlap.
#pragma unroll
    for (int off = 16; off > 0; off >>= 1) {
        s1 += __shfl_xor_sync(0xFFFFFFFFu, s1, off);
        s2 += __shfl_xor_sync(0xFFFFFFFFu, s2, off);
    }

    // --- scalar pipeline: out_i = F * w_i * p_i with F from the two row norms ---
    const float r1 = sqrtf(s1);                    // ||params||
    const float u_norm = fmaxf(r1, MIN_NORM);
    const float a = tanhf(SQRT_C * u_norm) / (SQRT_C * u_norm);  // expmap0 scale
    const float x_norm = fmaxf(a * r1, MIN_NORM);                // ||x|| clamped
    const float mx_norm = a * sqrtf(s2);                         // ||mx|| (NOT clamped)

    const float at1 = artanh_clamped(SQRT_C * x_norm);
    const float b = tanhf(mx_norm / x_norm * at1) / (mx_norm * SQRT_C);  // mobius scale
    const float res_norm = b * mx_norm;                                   // ||res||

    const float y_norm = fmaxf(res_norm, MIN_NORM);
    const float maxnorm = (1.0f - 0.001f) / SQRT_C;              // 9.99
    const float g = (y_norm > maxnorm) ? (maxnorm / y_norm) : 1.0f;  // project
    const float yn2 = fmaxf(g * res_norm, MIN_NORM);             // ||y|| clamped
    const float h = artanh_clamped(SQRT_C * yn2) / (yn2 * SQRT_C);   // logmap0 scale

    const float F = h * g * b * a;

#pragma unroll
    for (int j = 0; j < 4; j++) {
        float4 m = mv[j];
        float4 o;
        o.x = F * m.x;
        o.y = F * m.y;
        o.z = F * m.z;
        o.w = F * m.w;
        __stcs(&o4[j * 32 + lane], o);
    }
}

extern "C" void kernel_launch(void* const* d_in, const int* in_sizes, int n_in,
                              void* d_out, int out_size) {
    const float* params  = (const float*)d_in[0];
    const float* weights = (const float*)d_in[1];
    float* out = (float*)d_out;

    const int n_rows = in_sizes[0] / D;   // 131072
    const int grid = (n_rows + WARPS_PER_BLOCK - 1) / WARPS_PER_BLOCK;
    hyp_adapter_kernel<<<grid, THREADS>>>(params, weights, out, n_rows);
}